// round 4
// baseline (speedup 1.0000x reference)
#include <cuda_runtime.h>
#include <cuda_bf16.h>

// ---------------- constants ----------------
#define T_LEN (1 << 21)          // 2,097,152
#define B_CH  8192               // chains (256 steps each)
#define NPRE  2048               // k_pre blocks
#define NREF  64                 // refine blocks

// ---------------- device scratch ----------------
__device__ float4 g_tt[T_LEN + 1024];   // transposed (tp*350, tp/350, tn, tn/350); padded
__device__ float2 g_pe[T_LEN + 1024];   // transposed (pn, en); padded
__device__ float  g_send[2][B_CH];      // ping-pong block end states
__device__ float  g_prepart[NPRE * 4];  // Σpn, Σpn², Σen, Σen²
__device__ float  g_spart[NREF * 4];    // Σps, Σps², Σpc, Σpc²
__device__ float  g_stats[8];           // mu[4], inv_sigma[4]
__device__ int    g_done;               // ticket for fused stats finalize (reset each launch)

// transposed index: idx(C,i) = ((C>>5)<<13) | (i<<5) | (C&31)

// ---------------- shortened MUFU-free GR4J step ----------------
// Invariants: tp,tn <= tanh(10/350)=0.02857, 0 <= s < 350.
template <int OUT>
__device__ __forceinline__ float gr_step(float s, float tp350, float tpn,
                                         float tn, float tnn,
                                         float& ps_o, float& pc_o) {
    const float INV = 1.0f / 350.0f;
    const float C49 = 4.0f / (9.0f * 350.0f);
    float a    = s * tpn;                 // r*tp            (s+4)
    float be   = fmaf(-s, tnn, tn);       // (1-r)*tn        (s+4)
    float r    = s * INV;                 //                 (s+4)
    float stn  = s * tn;                  //                 (s+4)
    float aa   = a * a,   oma = 1.0f - a;            //      (s+8)
    float bb   = be * be, omb = 1.0f - be;           //      (s+8)
    float hp   = fmaf(aa, oma, oma);      // 1/(1+a)         (s+12)
    float he   = fmaf(bb, omb, omb);      // 1/(1+be)        (s+12)
    float omr2 = fmaf(-r, r, 1.0f);                  //      (s+8)
    float psA  = omr2 * tp350;                       //      (s+12)
    float A    = fmaf(psA, hp, s);        // s + ps          (s+16)
    float es   = ((2.0f - r) * stn) * he;            //      (s+16)
    float s1   = A - es;                             //      (s+20)
    float y    = s1 * C49;
    float y2   = y * y;
    float u    = y2 * y2;                            //      (s1+12)
    // Q(u) = 1 - u/4 + 5u^2/32 - 15u^3/128 (+O(u^4)), u <= 0.044
    float w1   = fmaf(u, -0.25f, 1.0f);
    float w2   = fmaf(u, -0.1171875f, 0.15625f);
    float u2   = u * u;
    float Q    = fmaf(u2, w2, w1);                   //      (s1+20)
    float s2   = s1 * Q;                             //      (s1+24)
    if (OUT) { ps_o = psA * hp; pc_o = s1 - s2; }    // off-chain
    return s2;
}

// ---------------- prologue: relu + tanh series + transpose + pn/en stats ----------------
__global__ void __launch_bounds__(256) k_pre(const float2* __restrict__ x) {
    __shared__ float4 t4[32][33];
    __shared__ float2 t2[32][33];
    __shared__ float  red[4][256];
    int bid = blockIdx.x;
    int c0  = (bid >> 3) << 5;       // 32-chain group base
    int i0  = (bid & 7) << 5;        // 32-step tile base
    int tid = threadIdx.x;
    float a0 = 0.f, a1 = 0.f, a2 = 0.f, a3 = 0.f;
#pragma unroll
    for (int k = 0; k < 4; k++) {
        int e  = tid + (k << 8);
        int cc = e >> 5, ii = e & 31;
        float2 v = x[(c0 + cc) * 256 + i0 + ii];          // coalesced
        float pn = fmaxf(v.x - v.y, 0.0f);
        float en = fmaxf(v.y - v.x, 0.0f);
        // tanh(z) = z(1 - z^2/3 + 2z^4/15), z <= 0.0286
        float zp = pn * (1.0f / 350.0f), zp2 = zp * zp;
        float tp = zp * fmaf(zp2, fmaf(zp2, 0.13333333f, -0.33333333f), 1.0f);
        float ze = en * (1.0f / 350.0f), ze2 = ze * ze;
        float tn = ze * fmaf(ze2, fmaf(ze2, 0.13333333f, -0.33333333f), 1.0f);
        t4[cc][ii] = make_float4(tp * 350.0f, tp * (1.0f / 350.0f), tn, tn * (1.0f / 350.0f));
        t2[cc][ii] = make_float2(pn, en);
        a0 += pn; a1 = fmaf(pn, pn, a1);
        a2 += en; a3 = fmaf(en, en, a3);
    }
    __syncthreads();
#pragma unroll
    for (int k = 0; k < 4; k++) {
        int e  = tid + (k << 8);
        int ii = e >> 5, cc = e & 31;
        int gi = ((c0 >> 5) << 13) + ((i0 + ii) << 5) + cc;
        g_tt[gi] = t4[cc][ii];                             // coalesced
        g_pe[gi] = t2[cc][ii];
    }
    red[0][tid] = a0; red[1][tid] = a1; red[2][tid] = a2; red[3][tid] = a3;
    __syncthreads();
    for (int o = 128; o > 0; o >>= 1) {
        if (tid < o) {
            red[0][tid] += red[0][tid + o]; red[1][tid] += red[1][tid + o];
            red[2][tid] += red[2][tid + o]; red[3][tid] += red[3][tid + o];
        }
        __syncthreads();
    }
    if (tid < 4) g_prepart[bid * 4 + tid] = red[tid][0];
}

// ---------------- refine pass (STATS variant fuses the global finalize) ----------------
template <int FIRST, int STATS>
__global__ void __launch_bounds__(128) k_refine(int srcIdx, int dstIdx) {
    int C = blockIdx.x * 128 + threadIdx.x;
    const float4* p = g_tt + (((C >> 5) << 13) | (C & 31));
    float s = (FIRST || C == 0) ? 0.0f : g_send[srcIdx][C - 1];
    float q0 = 0.f, q1 = 0.f, q2 = 0.f, q3 = 0.f;
    float4 A[8], B[8];
#pragma unroll
    for (int k = 0; k < 8; k++) A[k] = __ldg(&p[k << 5]);
#pragma unroll
    for (int k = 0; k < 8; k++) B[k] = __ldg(&p[(8 + k) << 5]);
#pragma unroll 1
    for (int i0 = 0; i0 < 256; i0 += 16) {
#pragma unroll
        for (int k = 0; k < 8; k++) {
            float ps, pc;
            s = gr_step<STATS>(s, A[k].x, A[k].y, A[k].z, A[k].w, ps, pc);
            if (STATS) { q0 += ps; q1 = fmaf(ps, ps, q1); q2 += pc; q3 = fmaf(pc, pc, q3); }
        }
#pragma unroll
        for (int k = 0; k < 8; k++) A[k] = __ldg(&p[(i0 + 16 + k) << 5]);  // pad absorbs overrun
#pragma unroll
        for (int k = 0; k < 8; k++) {
            float ps, pc;
            s = gr_step<STATS>(s, B[k].x, B[k].y, B[k].z, B[k].w, ps, pc);
            if (STATS) { q0 += ps; q1 = fmaf(ps, ps, q1); q2 += pc; q3 = fmaf(pc, pc, q3); }
        }
#pragma unroll
        for (int k = 0; k < 8; k++) B[k] = __ldg(&p[(i0 + 24 + k) << 5]);
    }
    g_send[dstIdx][C] = s;

    if (STATS) {
        __shared__ float rd[4][128];
        __shared__ int   lastf;
        int tx = threadIdx.x;
        rd[0][tx] = q0; rd[1][tx] = q1; rd[2][tx] = q2; rd[3][tx] = q3;
        __syncthreads();
        for (int o = 64; o > 0; o >>= 1) {
            if (tx < o) {
                rd[0][tx] += rd[0][tx + o]; rd[1][tx] += rd[1][tx + o];
                rd[2][tx] += rd[2][tx + o]; rd[3][tx] += rd[3][tx + o];
            }
            __syncthreads();
        }
        if (tx < 4) g_spart[blockIdx.x * 4 + tx] = rd[tx][0];
        __threadfence();
        if (tx == 0) lastf = (atomicAdd(&g_done, 1) == NREF - 1);
        __syncthreads();
        if (lastf) {
            __threadfence();
            __shared__ float sd[8][128];
            float acc[8] = {0, 0, 0, 0, 0, 0, 0, 0};
            for (int b = tx; b < NPRE; b += 128) {
                acc[0] += g_prepart[b * 4 + 0]; acc[1] += g_prepart[b * 4 + 1];
                acc[2] += g_prepart[b * 4 + 2]; acc[3] += g_prepart[b * 4 + 3];
            }
            if (tx < NREF) {
                acc[4] = g_spart[tx * 4 + 0]; acc[5] = g_spart[tx * 4 + 1];
                acc[6] = g_spart[tx * 4 + 2]; acc[7] = g_spart[tx * 4 + 3];
            }
#pragma unroll
            for (int k = 0; k < 8; k++) sd[k][tx] = acc[k];
            __syncthreads();
            for (int o = 64; o > 0; o >>= 1) {
                if (tx < o) {
#pragma unroll
                    for (int k = 0; k < 8; k++) sd[k][tx] += sd[k][tx + o];
                }
                __syncthreads();
            }
            if (tx == 0) {
                const float invT = 1.0f / (float)T_LEN;
                float S[4]  = {sd[0][0], sd[2][0], sd[4][0], sd[6][0]};
                float S2[4] = {sd[1][0], sd[3][0], sd[5][0], sd[7][0]};
#pragma unroll
                for (int k = 0; k < 4; k++) {
                    float mu  = S[k] * invT;
                    float var = fmaxf(S2[k] * invT - mu * mu, 0.0f);
                    g_stats[k]     = mu;
                    g_stats[4 + k] = 1.0f / sqrtf(var);
                }
                g_done = 0;   // reset ticket for next graph replay
            }
        }
    }
}

// ---------------- final pass: 8 steps, stage normalized rows, prefetch ----------------
__device__ __forceinline__ void f_phase(float& s, float4* TB, float2* PB,
                                        const float4* pt, const float2* pp, int pre,
                                        float4 (*tout)[33], float (*tss)[33],
                                        int lane, int off, const float* st) {
#pragma unroll
    for (int k = 0; k < 8; k++) {
        float ps, pc;
        s = gr_step<1>(s, TB[k].x, TB[k].y, TB[k].z, TB[k].w, ps, pc);
        tout[lane][off + k] = make_float4((PB[k].x - st[0]) * st[4],
                                          (PB[k].y - st[1]) * st[5],
                                          (ps - st[2]) * st[6],
                                          (pc - st[3]) * st[7]);
        tss[lane][off + k] = s;
    }
#pragma unroll
    for (int k = 0; k < 8; k++) {
        TB[k] = __ldg(&pt[(pre + k) << 5]);
        PB[k] = __ldg(&pp[(pre + k) << 5]);
    }
}

__global__ void __launch_bounds__(32) k_final(float4* __restrict__ out, float* __restrict__ ss) {
    __shared__ float4 tout[32][33];
    __shared__ float  tss[32][33];
    int lane = threadIdx.x;
    int C = (blockIdx.x << 5) + lane;
    const float4* pt = g_tt + (blockIdx.x << 13) + lane;
    const float2* pp = g_pe + (blockIdx.x << 13) + lane;
    float s = (C == 0) ? 0.0f : g_send[1][C - 1];
    float st[8];
#pragma unroll
    for (int k = 0; k < 8; k++) st[k] = g_stats[k];
    float4 A[8], B[8];
    float2 PA[8], PB[8];
#pragma unroll
    for (int k = 0; k < 8; k++) { A[k] = __ldg(&pt[k << 5]);       PA[k] = __ldg(&pp[k << 5]); }
#pragma unroll
    for (int k = 0; k < 8; k++) { B[k] = __ldg(&pt[(8 + k) << 5]); PB[k] = __ldg(&pp[(8 + k) << 5]); }
    int rowbase = blockIdx.x << 13;
#pragma unroll 1
    for (int t0 = 0; t0 < 256; t0 += 32) {
        f_phase(s, A, PA, pt, pp, t0 + 16, tout, tss, lane, 0,  st);
        f_phase(s, B, PB, pt, pp, t0 + 24, tout, tss, lane, 8,  st);
        f_phase(s, A, PA, pt, pp, t0 + 32, tout, tss, lane, 16, st);
        f_phase(s, B, PB, pt, pp, t0 + 40, tout, tss, lane, 24, st);
        __syncwarp();
#pragma unroll 1
        for (int j = 0; j < 32; j++) {
            out[rowbase + j * 256 + t0 + lane] = tout[j][lane];   // 512B coalesced
            ss [rowbase + j * 256 + t0 + lane] = tss[j][lane];    // 128B coalesced
        }
        __syncwarp();
    }
}

// ---------------- launch ----------------
extern "C" void kernel_launch(void* const* d_in, const int* in_sizes, int n_in,
                              void* d_out, int out_size) {
    (void)in_sizes; (void)n_in; (void)out_size;
    const float2* x = (const float2*)d_in[0];
    float* out = (float*)d_out;                  // (T,4) normalized
    float* ssp = out + 4 * (size_t)T_LEN;        // (T,1) state trace

    k_pre<<<NPRE, 256>>>(x);
    k_refine<1, 0><<<NREF, 128>>>(0, 0);
    k_refine<0, 0><<<NREF, 128>>>(0, 1);
    k_refine<0, 0><<<NREF, 128>>>(1, 0);
    k_refine<0, 1><<<NREF, 128>>>(0, 1);   // stats pass + fused finalize
    k_final<<<B_CH / 32, 32>>>((float4*)out, ssp);
}

// round 5
// speedup vs baseline: 1.1776x; 1.1776x over previous
#include <cuda_runtime.h>
#include <cuda_bf16.h>

// ---------------- constants ----------------
#define T_LEN (1 << 21)          // 2,097,152
#define B_CH  8192               // chains (256 steps each)
#define NPRE  2048               // k_pre blocks
#define NREF  64                 // refine blocks

// ---------------- device scratch ----------------
__device__ float4 g_tt[T_LEN + 1024];   // transposed (tp*350, tp/350, tn, tn/350); padded
__device__ float2 g_pe[T_LEN + 1024];   // transposed (pn, en); padded
__device__ float  g_send[2][B_CH];      // ping-pong block end states
__device__ float  g_ck[4][B_CH];        // 64-step checkpoints from stats pass
__device__ float  g_prepart[NPRE * 4];  // Σpn, Σpn², Σen, Σen²
__device__ float  g_spart[NREF * 4];    // Σps, Σps², Σpc, Σpc²
__device__ float  g_stats[8];           // mu[4], inv_sigma[4]

// transposed index: idx(C,i) = ((C>>5)<<13) | (i<<5) | (C&31)

// ---------------- MUFU-free GR4J step (quad operands) ----------------
// Invariants: tp,tn <= tanh(10/350)=0.02857, 0 <= s < 350.
template <int OUT>
__device__ __forceinline__ float gr_step(float s, float tp350, float tpn,
                                         float tn, float tnn,
                                         float& ps_o, float& pc_o) {
    const float INV = 1.0f / 350.0f;
    const float C49 = 4.0f / (9.0f * 350.0f);
    float a    = s * tpn;                 // r*tp
    float be   = fmaf(-s, tnn, tn);       // (1-r)*tn
    float r    = s * INV;
    float stn  = s * tn;
    float aa   = a * a,   oma = 1.0f - a;
    float bb   = be * be, omb = 1.0f - be;
    float hp   = fmaf(aa, oma, oma);      // 1/(1+a)  + O(a^3)
    float he   = fmaf(bb, omb, omb);      // 1/(1+be)
    float omr2 = fmaf(-r, r, 1.0f);
    float psA  = omr2 * tp350;
    float A    = fmaf(psA, hp, s);        // s + ps
    float es   = ((2.0f - r) * stn) * he;
    float s1   = A - es;
    float y    = s1 * C49;
    float y2   = y * y;
    float u    = y2 * y2;
    // Q(u) = 1 - u/4 + 5u^2/32 - 15u^3/128, u <= 0.044
    float w1   = fmaf(u, -0.25f, 1.0f);
    float w2   = fmaf(u, -0.1171875f, 0.15625f);
    float u2   = u * u;
    float Q    = fmaf(u2, w2, w1);
    float s2   = s1 * Q;
    if (OUT) { ps_o = psA * hp; pc_o = s1 - s2; }   // off-chain
    return s2;
}

// tanh series shared by k_pre and k_out (must be bit-identical in both)
__device__ __forceinline__ float tanh_small(float z) {
    float z2 = z * z;
    return z * fmaf(z2, fmaf(z2, 0.13333333f, -0.33333333f), 1.0f);
}

// ---------------- prologue: relu + tanh + transpose + pn/en stats ----------------
__global__ void __launch_bounds__(256) k_pre(const float2* __restrict__ x) {
    __shared__ float4 t4[32][33];
    __shared__ float2 t2[32][33];
    __shared__ float  red[4][256];
    int bid = blockIdx.x;
    int c0  = (bid >> 3) << 5;       // 32-chain group base
    int i0  = (bid & 7) << 5;        // 32-step tile base
    int tid = threadIdx.x;
    float a0 = 0.f, a1 = 0.f, a2 = 0.f, a3 = 0.f;
#pragma unroll
    for (int k = 0; k < 4; k++) {
        int e  = tid + (k << 8);
        int cc = e >> 5, ii = e & 31;
        float2 v = x[(c0 + cc) * 256 + i0 + ii];          // coalesced
        float pn = fmaxf(v.x - v.y, 0.0f);
        float en = fmaxf(v.y - v.x, 0.0f);
        float tp = tanh_small(pn * (1.0f / 350.0f));
        float tn = tanh_small(en * (1.0f / 350.0f));
        t4[cc][ii] = make_float4(tp * 350.0f, tp * (1.0f / 350.0f), tn, tn * (1.0f / 350.0f));
        t2[cc][ii] = make_float2(pn, en);
        a0 += pn; a1 = fmaf(pn, pn, a1);
        a2 += en; a3 = fmaf(en, en, a3);
    }
    __syncthreads();
#pragma unroll
    for (int k = 0; k < 4; k++) {
        int e  = tid + (k << 8);
        int ii = e >> 5, cc = e & 31;
        int gi = ((c0 >> 5) << 13) + ((i0 + ii) << 5) + cc;
        g_tt[gi] = t4[cc][ii];                             // coalesced
        g_pe[gi] = t2[cc][ii];
    }
    red[0][tid] = a0; red[1][tid] = a1; red[2][tid] = a2; red[3][tid] = a3;
    __syncthreads();
    for (int o = 128; o > 0; o >>= 1) {
        if (tid < o) {
            red[0][tid] += red[0][tid + o]; red[1][tid] += red[1][tid + o];
            red[2][tid] += red[2][tid + o]; red[3][tid] += red[3][tid + o];
        }
        __syncthreads();
    }
    if (tid < 4) g_prepart[bid * 4 + tid] = red[tid][0];
}

// ---------------- refine pass (STATS also emits checkpoints + partials) ----------------
template <int FIRST, int STATS>
__global__ void __launch_bounds__(128) k_refine(int srcIdx, int dstIdx) {
    int C = blockIdx.x * 128 + threadIdx.x;
    const float4* p = g_tt + (((C >> 5) << 13) | (C & 31));
    float s = (FIRST || C == 0) ? 0.0f : g_send[srcIdx][C - 1];
    float q0 = 0.f, q1 = 0.f, q2 = 0.f, q3 = 0.f;
    if (STATS) g_ck[0][C] = s;
    float4 A[8], B[8];
#pragma unroll
    for (int k = 0; k < 8; k++) A[k] = __ldg(&p[k << 5]);
#pragma unroll
    for (int k = 0; k < 8; k++) B[k] = __ldg(&p[(8 + k) << 5]);
#pragma unroll 1
    for (int i0 = 0; i0 < 256; i0 += 16) {
#pragma unroll
        for (int k = 0; k < 8; k++) {
            float ps, pc;
            s = gr_step<STATS>(s, A[k].x, A[k].y, A[k].z, A[k].w, ps, pc);
            if (STATS) { q0 += ps; q1 = fmaf(ps, ps, q1); q2 += pc; q3 = fmaf(pc, pc, q3); }
        }
#pragma unroll
        for (int k = 0; k < 8; k++) A[k] = __ldg(&p[(i0 + 16 + k) << 5]);  // pad absorbs overrun
#pragma unroll
        for (int k = 0; k < 8; k++) {
            float ps, pc;
            s = gr_step<STATS>(s, B[k].x, B[k].y, B[k].z, B[k].w, ps, pc);
            if (STATS) { q0 += ps; q1 = fmaf(ps, ps, q1); q2 += pc; q3 = fmaf(pc, pc, q3); }
        }
#pragma unroll
        for (int k = 0; k < 8; k++) B[k] = __ldg(&p[(i0 + 24 + k) << 5]);
        if (STATS) {
            int nx = i0 + 16;
            if ((nx & 63) == 0 && nx < 256) g_ck[nx >> 6][C] = s;  // 64-step checkpoint
        }
    }
    if (!STATS) g_send[dstIdx][C] = s;
    if (STATS) {
        __shared__ float rd[4][128];
        int tx = threadIdx.x;
        rd[0][tx] = q0; rd[1][tx] = q1; rd[2][tx] = q2; rd[3][tx] = q3;
        __syncthreads();
        for (int o = 64; o > 0; o >>= 1) {
            if (tx < o) {
                rd[0][tx] += rd[0][tx + o]; rd[1][tx] += rd[1][tx + o];
                rd[2][tx] += rd[2][tx + o]; rd[3][tx] += rd[3][tx + o];
            }
            __syncthreads();
        }
        if (tx < 4) g_spart[blockIdx.x * 4 + tx] = rd[tx][0];
    }
}

// ---------------- combine partials -> mu / inv_sigma ----------------
__global__ void __launch_bounds__(256) k_statsk() {
    __shared__ float sd[8][256];
    int tx = threadIdx.x;
    float acc[8] = {0, 0, 0, 0, 0, 0, 0, 0};
    for (int b = tx; b < NPRE; b += 256) {
        acc[0] += g_prepart[b * 4 + 0]; acc[1] += g_prepart[b * 4 + 1];
        acc[2] += g_prepart[b * 4 + 2]; acc[3] += g_prepart[b * 4 + 3];
    }
    if (tx < NREF) {
        acc[4] = g_spart[tx * 4 + 0]; acc[5] = g_spart[tx * 4 + 1];
        acc[6] = g_spart[tx * 4 + 2]; acc[7] = g_spart[tx * 4 + 3];
    }
#pragma unroll
    for (int k = 0; k < 8; k++) sd[k][tx] = acc[k];
    __syncthreads();
    for (int o = 128; o > 0; o >>= 1) {
        if (tx < o) {
#pragma unroll
            for (int k = 0; k < 8; k++) sd[k][tx] += sd[k][tx + o];
        }
        __syncthreads();
    }
    if (tx == 0) {
        const float invT = 1.0f / (float)T_LEN;
        float S[4]  = {sd[0][0], sd[2][0], sd[4][0], sd[6][0]};
        float S2[4] = {sd[1][0], sd[3][0], sd[5][0], sd[7][0]};
#pragma unroll
        for (int k = 0; k < 4; k++) {
            float mu  = S[k] * invT;
            float var = fmaxf(S2[k] * invT - mu * mu, 0.0f);
            g_stats[k]     = mu;
            g_stats[4 + k] = 1.0f / sqrtf(var);
        }
    }
}

// ---------------- output pass: 64 steps/thread from checkpoints (4x parallel) ------
__device__ __forceinline__ void o_phase(float& s, float2* PB, const float2* pp, int pre,
                                        float4 (*tout)[33], float (*tss)[33],
                                        int lane, int off, const float* st) {
#pragma unroll
    for (int k = 0; k < 8; k++) {
        float pn = PB[k].x, en = PB[k].y;
        // EXACT same expressions as k_pre (bit-identical quads)
        float tp = tanh_small(pn * (1.0f / 350.0f));
        float tn = tanh_small(en * (1.0f / 350.0f));
        float tp350 = tp * 350.0f;
        float tpn   = tp * (1.0f / 350.0f);
        float tnn   = tn * (1.0f / 350.0f);
        float ps, pc;
        s = gr_step<1>(s, tp350, tpn, tn, tnn, ps, pc);
        tout[lane][off + k] = make_float4((pn - st[0]) * st[4],
                                          (en - st[1]) * st[5],
                                          (ps - st[2]) * st[6],
                                          (pc - st[3]) * st[7]);
        tss[lane][off + k] = s;
    }
#pragma unroll
    for (int k = 0; k < 8; k++) PB[k] = __ldg(&pp[(pre + k) << 5]);
}

__global__ void __launch_bounds__(32) k_out(float4* __restrict__ out, float* __restrict__ ss) {
    __shared__ float4 tout[32][33];
    __shared__ float  tss[32][33];
    int lane = threadIdx.x;
    int cg = blockIdx.x >> 2;        // chain group (32 chains)
    int w  = blockIdx.x & 3;         // 64-step window
    int C  = (cg << 5) + lane;
    const float2* pp = g_pe + (cg << 13) + ((w << 6) << 5) + lane;
    float s = g_ck[w][C];
    float st[8];
#pragma unroll
    for (int k = 0; k < 8; k++) st[k] = g_stats[k];
    float2 PA[8], PB[8];
#pragma unroll
    for (int k = 0; k < 8; k++) PA[k] = __ldg(&pp[k << 5]);
#pragma unroll
    for (int k = 0; k < 8; k++) PB[k] = __ldg(&pp[(8 + k) << 5]);
    int rowbase = (cg << 13) + (w << 6);   // row index of (chain cg*32, step w*64)
#pragma unroll 1
    for (int t0 = 0; t0 < 64; t0 += 32) {
        o_phase(s, PA, pp, t0 + 16, tout, tss, lane, 0,  st);
        o_phase(s, PB, pp, t0 + 24, tout, tss, lane, 8,  st);
        o_phase(s, PA, pp, t0 + 32, tout, tss, lane, 16, st);  // pad absorbs overrun
        o_phase(s, PB, pp, t0 + 40, tout, tss, lane, 24, st);
        __syncwarp();
#pragma unroll 1
        for (int j = 0; j < 32; j++) {
            out[rowbase + j * 256 + t0 + lane] = tout[j][lane];   // 512B coalesced
            ss [rowbase + j * 256 + t0 + lane] = tss[j][lane];    // 128B coalesced
        }
        __syncwarp();
    }
}

// ---------------- launch ----------------
extern "C" void kernel_launch(void* const* d_in, const int* in_sizes, int n_in,
                              void* d_out, int out_size) {
    (void)in_sizes; (void)n_in; (void)out_size;
    const float2* x = (const float2*)d_in[0];
    float* out = (float*)d_out;                  // (T,4) normalized
    float* ssp = out + 4 * (size_t)T_LEN;        // (T,1) state trace

    k_pre<<<NPRE, 256>>>(x);
    k_refine<1, 0><<<NREF, 128>>>(0, 0);
    k_refine<0, 0><<<NREF, 128>>>(0, 1);
    k_refine<0, 0><<<NREF, 128>>>(1, 0);
    k_refine<0, 1><<<NREF, 128>>>(0, 1);   // stats + 64-step checkpoints (history 768)
    k_statsk<<<1, 256>>>();
    k_out<<<4 * (B_CH / 32), 32>>>((float4*)out, ssp);
}

// round 6
// speedup vs baseline: 1.5824x; 1.3437x over previous
#include <cuda_runtime.h>
#include <cuda_bf16.h>

// ---------------- constants ----------------
#define T_LEN (1 << 21)          // 2,097,152
#define B_CH  8192               // chains (256 steps each)
#define NPRE  2048               // k_pre blocks
#define NREF  64                 // refine blocks
#define S_EQ  166.0f             // stationary-state init for relaxation

// ---------------- device scratch ----------------
__device__ float g_d[T_LEN + 2048];     // transposed d = P - E; padded for prefetch overrun
__device__ float g_send[2][B_CH];       // ping-pong block end states
__device__ float g_ck[4][B_CH];         // 64-step checkpoints from stats pass
__device__ float g_prepart[NPRE * 4];   // Σpn, Σpn², Σen, Σen²
__device__ float g_spart[NREF * 4];     // Σps, Σps², Σpc, Σpc²
__device__ float g_stats[8];            // mu[4], inv_sigma[4]

// transposed index: idx(C,i) = ((C>>5)<<13) | (i<<5) | (C&31)

// ---------------- forcing -> step operands (shared by ALL passes; bit-identical) ----
__device__ __forceinline__ void make_ops(float d, float& tp350, float& tpn,
                                         float& tn, float& tnn) {
    const float INV = 1.0f / 350.0f;
    float pn  = fmaxf(d, 0.0f);
    float en  = fmaxf(-d, 0.0f);
    float mp  = pn * INV;
    float mp2 = mp * mp;
    float gp  = fmaf(mp2, fmaf(mp2, 0.13333333f, -0.33333333f), 1.0f); // tanh(z)/z
    float me  = en * INV;
    float me2 = me * me;
    float ge  = fmaf(me2, fmaf(me2, 0.13333333f, -0.33333333f), 1.0f);
    tp350 = pn * gp;            // tanh(pn/350)*350
    tpn   = (mp * gp) * INV;    // tanh(pn/350)/350
    tn    = me * ge;            // tanh(en/350)
    tnn   = tn * INV;
}

// ---------------- MUFU-free GR4J step ----------------
// Invariants: tp,tn <= tanh(10/350)=0.02857, 0 <= s < 350.
template <int OUT>
__device__ __forceinline__ float gr_step(float s, float tp350, float tpn,
                                         float tn, float tnn,
                                         float& ps_o, float& pc_o) {
    const float INV = 1.0f / 350.0f;
    const float C49 = 4.0f / (9.0f * 350.0f);
    float a    = s * tpn;                 // r*tp
    float be   = fmaf(-s, tnn, tn);       // (1-r)*tn
    float r    = s * INV;
    float stn  = s * tn;
    float aa   = a * a,   oma = 1.0f - a;
    float bb   = be * be, omb = 1.0f - be;
    float hp   = fmaf(aa, oma, oma);      // 1/(1+a)
    float he   = fmaf(bb, omb, omb);      // 1/(1+be)
    float omr2 = fmaf(-r, r, 1.0f);
    float psA  = omr2 * tp350;
    float A    = fmaf(psA, hp, s);        // s + ps
    float es   = ((2.0f - r) * stn) * he;
    float s1   = A - es;
    float y    = s1 * C49;
    float y2   = y * y;
    float u    = y2 * y2;
    // Q(u) = 1 - u/4 + 5u^2/32 - 15u^3/128, u <= 0.044
    float w1   = fmaf(u, -0.25f, 1.0f);
    float w2   = fmaf(u, -0.1171875f, 0.15625f);
    float u2   = u * u;
    float Q    = fmaf(u2, w2, w1);
    float s2   = s1 * Q;
    if (OUT) { ps_o = psA * hp; pc_o = s1 - s2; }   // off-chain
    return s2;
}

// ---------------- prologue: d = P-E, transpose, pn/en stats ----------------
__global__ void __launch_bounds__(256) k_pre(const float2* __restrict__ x) {
    __shared__ float tile[32][33];
    __shared__ float red[4][256];
    int bid = blockIdx.x;
    int c0  = (bid >> 3) << 5;       // 32-chain group base
    int i0  = (bid & 7) << 5;        // 32-step tile base
    int tid = threadIdx.x;
    float a0 = 0.f, a1 = 0.f, a2 = 0.f, a3 = 0.f;
#pragma unroll
    for (int k = 0; k < 4; k++) {
        int e  = tid + (k << 8);
        int cc = e >> 5, ii = e & 31;
        float2 v = x[(c0 + cc) * 256 + i0 + ii];          // coalesced
        float d  = v.x - v.y;
        float pn = fmaxf(d, 0.0f);
        float en = fmaxf(-d, 0.0f);
        tile[cc][ii] = d;
        a0 += pn; a1 = fmaf(pn, pn, a1);
        a2 += en; a3 = fmaf(en, en, a3);
        __syncthreads();                       // reuse tile across k
        int ii2 = e >> 5, cc2 = e & 31;
        (void)ii2; (void)cc2;
        __syncthreads();
    }
    // (re-stage once: simpler two-phase path below)
    __syncthreads();
#pragma unroll
    for (int k = 0; k < 4; k++) {
        int e  = tid + (k << 8);
        int cc = e >> 5, ii = e & 31;
        float2 v = x[(c0 + cc) * 256 + i0 + ii];
        tile[cc][ii] = v.x - v.y;
    }
    __syncthreads();
#pragma unroll
    for (int k = 0; k < 4; k++) {
        int e  = tid + (k << 8);
        int ii = e >> 5, cc = e & 31;
        g_d[((c0 >> 5) << 13) + ((i0 + ii) << 5) + cc] = tile[cc][ii];  // coalesced
    }
    red[0][tid] = a0; red[1][tid] = a1; red[2][tid] = a2; red[3][tid] = a3;
    __syncthreads();
    for (int o = 128; o > 0; o >>= 1) {
        if (tid < o) {
            red[0][tid] += red[0][tid + o]; red[1][tid] += red[1][tid + o];
            red[2][tid] += red[2][tid + o]; red[3][tid] += red[3][tid + o];
        }
        __syncthreads();
    }
    if (tid < 4) g_prepart[bid * 4 + tid] = red[tid][0];
}

// ---------------- refine pass (STATS also emits checkpoints + partials) ----------------
template <int FIRST, int STATS>
__global__ void __launch_bounds__(128) k_refine(int srcIdx, int dstIdx) {
    int C = blockIdx.x * 128 + threadIdx.x;
    const float* p = g_d + (((C >> 5) << 13) | (C & 31));
    float s = (C == 0) ? 0.0f : (FIRST ? S_EQ : g_send[srcIdx][C - 1]);
    float q0 = 0.f, q1 = 0.f, q2 = 0.f, q3 = 0.f;
    if (STATS) g_ck[0][C] = s;
    float A[8], B[8];
#pragma unroll
    for (int k = 0; k < 8; k++) A[k] = __ldg(&p[k << 5]);
#pragma unroll
    for (int k = 0; k < 8; k++) B[k] = __ldg(&p[(8 + k) << 5]);
#pragma unroll 1
    for (int i0 = 0; i0 < 256; i0 += 16) {
#pragma unroll
        for (int k = 0; k < 8; k++) {
            float t3, tpn, tn, tnn, ps, pc;
            make_ops(A[k], t3, tpn, tn, tnn);
            s = gr_step<STATS>(s, t3, tpn, tn, tnn, ps, pc);
            if (STATS) { q0 += ps; q1 = fmaf(ps, ps, q1); q2 += pc; q3 = fmaf(pc, pc, q3); }
        }
#pragma unroll
        for (int k = 0; k < 8; k++) A[k] = __ldg(&p[(i0 + 16 + k) << 5]);  // pad absorbs overrun
#pragma unroll
        for (int k = 0; k < 8; k++) {
            float t3, tpn, tn, tnn, ps, pc;
            make_ops(B[k], t3, tpn, tn, tnn);
            s = gr_step<STATS>(s, t3, tpn, tn, tnn, ps, pc);
            if (STATS) { q0 += ps; q1 = fmaf(ps, ps, q1); q2 += pc; q3 = fmaf(pc, pc, q3); }
        }
#pragma unroll
        for (int k = 0; k < 8; k++) B[k] = __ldg(&p[(i0 + 24 + k) << 5]);
        if (STATS) {
            int nx = i0 + 16;
            if ((nx & 63) == 0 && nx < 256) g_ck[nx >> 6][C] = s;  // 64-step checkpoint
        }
    }
    if (!STATS) g_send[dstIdx][C] = s;
    if (STATS) {
        __shared__ float rd[4][128];
        int tx = threadIdx.x;
        rd[0][tx] = q0; rd[1][tx] = q1; rd[2][tx] = q2; rd[3][tx] = q3;
        __syncthreads();
        for (int o = 64; o > 0; o >>= 1) {
            if (tx < o) {
                rd[0][tx] += rd[0][tx + o]; rd[1][tx] += rd[1][tx + o];
                rd[2][tx] += rd[2][tx + o]; rd[3][tx] += rd[3][tx + o];
            }
            __syncthreads();
        }
        if (tx < 4) g_spart[blockIdx.x * 4 + tx] = rd[tx][0];
    }
}

// ---------------- combine partials -> mu / inv_sigma ----------------
__global__ void __launch_bounds__(256) k_statsk() {
    __shared__ float sd[8][256];
    int tx = threadIdx.x;
    float acc[8] = {0, 0, 0, 0, 0, 0, 0, 0};
    for (int b = tx; b < NPRE; b += 256) {
        acc[0] += g_prepart[b * 4 + 0]; acc[1] += g_prepart[b * 4 + 1];
        acc[2] += g_prepart[b * 4 + 2]; acc[3] += g_prepart[b * 4 + 3];
    }
    if (tx < NREF) {
        acc[4] = g_spart[tx * 4 + 0]; acc[5] = g_spart[tx * 4 + 1];
        acc[6] = g_spart[tx * 4 + 2]; acc[7] = g_spart[tx * 4 + 3];
    }
#pragma unroll
    for (int k = 0; k < 8; k++) sd[k][tx] = acc[k];
    __syncthreads();
    for (int o = 128; o > 0; o >>= 1) {
        if (tx < o) {
#pragma unroll
            for (int k = 0; k < 8; k++) sd[k][tx] += sd[k][tx + o];
        }
        __syncthreads();
    }
    if (tx == 0) {
        const float invT = 1.0f / (float)T_LEN;
        float S[4]  = {sd[0][0], sd[2][0], sd[4][0], sd[6][0]};
        float S2[4] = {sd[1][0], sd[3][0], sd[5][0], sd[7][0]};
#pragma unroll
        for (int k = 0; k < 4; k++) {
            float mu  = S[k] * invT;
            float var = fmaxf(S2[k] * invT - mu * mu, 0.0f);
            g_stats[k]     = mu;
            g_stats[4 + k] = 1.0f / sqrtf(var);
        }
    }
}

// ---------------- output pass: 64 steps/thread from checkpoints ----------------
__device__ __forceinline__ void o_phase(float& s, float* DB, const float* pp, int pre,
                                        float4 (*tout)[33], float (*tss)[33],
                                        int lane, int off, const float* st) {
#pragma unroll
    for (int k = 0; k < 8; k++) {
        float d  = DB[k];
        float pn = fmaxf(d, 0.0f);
        float en = fmaxf(-d, 0.0f);
        float t3, tpn, tn, tnn, ps, pc;
        make_ops(d, t3, tpn, tn, tnn);
        s = gr_step<1>(s, t3, tpn, tn, tnn, ps, pc);
        tout[lane][off + k] = make_float4((pn - st[0]) * st[4],
                                          (en - st[1]) * st[5],
                                          (ps - st[2]) * st[6],
                                          (pc - st[3]) * st[7]);
        tss[lane][off + k] = s;
    }
#pragma unroll
    for (int k = 0; k < 8; k++) DB[k] = __ldg(&pp[(pre + k) << 5]);
}

__global__ void __launch_bounds__(32) k_out(float4* __restrict__ out, float* __restrict__ ss) {
    __shared__ float4 tout[32][33];
    __shared__ float  tss[32][33];
    int lane = threadIdx.x;
    int cg = blockIdx.x >> 2;        // chain group (32 chains)
    int w  = blockIdx.x & 3;         // 64-step window
    int C  = (cg << 5) + lane;
    const float* pp = g_d + (cg << 13) + ((w << 6) << 5) + lane;
    float s = g_ck[w][C];
    float st[8];
#pragma unroll
    for (int k = 0; k < 8; k++) st[k] = g_stats[k];
    float DA[8], DB[8];
#pragma unroll
    for (int k = 0; k < 8; k++) DA[k] = __ldg(&pp[k << 5]);
#pragma unroll
    for (int k = 0; k < 8; k++) DB[k] = __ldg(&pp[(8 + k) << 5]);
    int rowbase = (cg << 13) + (w << 6);
#pragma unroll 1
    for (int t0 = 0; t0 < 64; t0 += 32) {
        o_phase(s, DA, pp, t0 + 16, tout, tss, lane, 0,  st);
        o_phase(s, DB, pp, t0 + 24, tout, tss, lane, 8,  st);
        o_phase(s, DA, pp, t0 + 32, tout, tss, lane, 16, st);  // pad absorbs overrun
        o_phase(s, DB, pp, t0 + 40, tout, tss, lane, 24, st);
        __syncwarp();
#pragma unroll 1
        for (int j = 0; j < 32; j++) {
            out[rowbase + j * 256 + t0 + lane] = tout[j][lane];   // 512B coalesced
            ss [rowbase + j * 256 + t0 + lane] = tss[j][lane];    // 128B coalesced
        }
        __syncwarp();
    }
}

// ---------------- launch ----------------
extern "C" void kernel_launch(void* const* d_in, const int* in_sizes, int n_in,
                              void* d_out, int out_size) {
    (void)in_sizes; (void)n_in; (void)out_size;
    const float2* x = (const float2*)d_in[0];
    float* out = (float*)d_out;                  // (T,4) normalized
    float* ssp = out + 4 * (size_t)T_LEN;        // (T,1) state trace

    k_pre<<<NPRE, 256>>>(x);
    k_refine<1, 0><<<NREF, 128>>>(0, 0);   // init at s*=166, history 256
    k_refine<0, 0><<<NREF, 128>>>(0, 1);   // history 512
    k_refine<0, 1><<<NREF, 128>>>(1, 0);   // stats + checkpoints (history 512 at entry)
    k_statsk<<<1, 256>>>();
    k_out<<<4 * (B_CH / 32), 32>>>((float4*)out, ssp);
}